// round 13
// baseline (speedup 1.0000x reference)
#include <cuda_runtime.h>
#include <cstdint>

#define BATCH 1024
#define NEL 32
#define NUP 16
#define NION 8
#define D1 256
#define D2 32
#define DION 64
#define DELION 32
#define EMB 64
#define FEAT 928
#define MULT_ELEMS (BATCH*NEL*NEL*EMB)   // 67108864

// K2 dynamic smem layout (floats)
#define K2_SW     0          // [2][2048] = 4096
#define K2_SHM    4096       // 2048
#define K2_SRED   6144       // [2][4][4][64] = 2048
#define K2_SPAIR  8192       // 2 x (4 rows x 32 j x 36 k) = 2*4608
#define K2_ROWPAD 36
#define K2_TILE   4608       // 4*32*36
#define K2_SMEM_BYTES ((8192 + 2*4608) * 4)         // 69632

__device__ float g_hmapped[BATCH*NEL*EMB];       // 8 MB

// rel err ~1e-6 tanh: 2 MUFU + few ALU
__device__ __forceinline__ float fast_tanh(float x) {
    float ax = fabsf(x);
    float e  = __expf(-2.0f * ax);
    float r  = __fdividef(1.0f - e, 1.0f + e);
    return copysignf(r, x);
}

__device__ __forceinline__ void cp16(void* dst_smem, const void* src) {
    unsigned d = (unsigned)__cvta_generic_to_shared(dst_smem);
    asm volatile("cp.async.cg.shared.global [%0], [%1], 16;\n" :: "r"(d), "l"(src));
}
#define CP_COMMIT() asm volatile("cp.async.commit_group;\n")
#define CP_WAIT0()  asm volatile("cp.async.wait_group 0;\n" ::: "memory")

// ---------------------------------------------------------------------------
// K13: fused h_mapped GEMM + spin averages + ion mapping + feats assembly.
// (round-10 version, measured 73us)
// ---------------------------------------------------------------------------
__global__ void __launch_bounds__(256, 3) k13_fused(
    const float* __restrict__ h_one,
    const float* __restrict__ W,      // (256,64)
    const float* __restrict__ bias,   // (64,)
    const float* __restrict__ h_ion,
    const float* __restrict__ h_el_ion,
    const float* __restrict__ W_ion, const float* __restrict__ b_ion,
    float* __restrict__ feats)
{
    __shared__ __align__(16) float sH[NEL*D1];       // 32 KB
    __shared__ float sI[NION*DION];                  // 2 KB
    __shared__ float sIon[NION*DELION];              // 1 KB
    int b = blockIdx.x;
    const float4* hb4 = (const float4*)(h_one + (size_t)b*NEL*D1);
    #pragma unroll
    for (int t = 0; t < 8; t++)
        ((float4*)sH)[threadIdx.x + t*256] = hb4[threadIdx.x + t*256];
    for (int t = threadIdx.x; t < NION*DION; t += 256)
        sI[t] = h_ion[(size_t)b*NION*DION + t];
    __syncthreads();

    // ion mapping: one (a,c) per thread
    {
        int c = threadIdx.x & 31;
        int a = threadIdx.x >> 5;
        float acc = __ldg(b_ion + c);
        #pragma unroll 4
        for (int k = 0; k < DION; k++)
            acc = fmaf(sI[a*DION + k], __ldg(W_ion + k*DELION + c), acc);
        sIon[a*DELION + c] = fast_tanh(acc);
    }

    // h_mapped GEMM: 4 rows x 2 cols per thread
    int et = threadIdx.x & 31;   int e0 = et*2;
    int it = threadIdx.x >> 5;

    float2 bv = __ldg((const float2*)(bias + e0));
    float2 acc[4];
    #pragma unroll
    for (int r = 0; r < 4; r++) acc[r] = bv;

    #pragma unroll 4
    for (int k = 0; k < D1; k += 4) {
        float h[4][4];
        #pragma unroll
        for (int r = 0; r < 4; r++) {
            float4 v = *(const float4*)&sH[(it*4 + r)*D1 + k];
            h[r][0] = v.x; h[r][1] = v.y; h[r][2] = v.z; h[r][3] = v.w;
        }
        #pragma unroll
        for (int t = 0; t < 4; t++) {
            float2 w = __ldg((const float2*)(W + (k + t)*EMB + e0));
            #pragma unroll
            for (int r = 0; r < 4; r++) {
                acc[r].x = fmaf(h[r][t], w.x, acc[r].x);
                acc[r].y = fmaf(h[r][t], w.y, acc[r].y);
            }
        }
    }
    float* o = g_hmapped + (size_t)b*NEL*EMB;
    #pragma unroll
    for (int r = 0; r < 4; r++) {
        float2 ov = make_float2(fast_tanh(acc[r].x), fast_tanh(acc[r].y));
        *(float2*)&o[(it*4 + r)*EMB + e0] = ov;
    }

    // spin averages of h_one (per-thread feature d)
    int d = threadIdx.x;
    float su = 0.f, sd = 0.f;
    #pragma unroll
    for (int i = 0; i < NUP; i++)  su += sH[i*D1 + d];
    #pragma unroll
    for (int i = NUP; i < NEL; i++) sd += sH[i*D1 + d];
    float au = su * (1.0f/NUP);
    float ad = sd * (1.0f/(NEL - NUP));

    __syncthreads();   // sIon ready

    // feats: h_one copy + tiles
    for (int i = 0; i < NEL; i++) {
        float* fb = feats + ((size_t)b*NEL + i)*FEAT;
        fb[d]        = sH[i*D1 + d];
        fb[D1 + d]   = au;
        fb[2*D1 + d] = ad;
    }

    // el_ion
    int c  = threadIdx.x & 31;
    int ig = threadIdx.x >> 5;
    #pragma unroll
    for (int r = 0; r < 4; r++) {
        int i = ig + r*8;
        const float* he = h_el_ion + (((size_t)b*NEL + i)*NION)*DELION;
        float acc2 = 0.f;
        #pragma unroll
        for (int a = 0; a < NION; a++)
            acc2 += he[a*DELION + c] * sIon[a*DELION + c];
        feats[((size_t)b*NEL + i)*FEAT + 896 + c] = acc2 * (1.0f/NION);
    }
}

// ---------------------------------------------------------------------------
// K2: pair GEMM + tanh + multiply -> el_el_mult, el_el, f_pairs.
// 512 threads, 4 i-rows/step (8 steps), thread tile 2j x 8e:
// per k = 2 W-wavefronts (8x16B dedup) + 2 pair broadcasts = 4 wf
// vs 16 FFMA-inst -> LSU at 50% of FMA.  Rows padded to 36 floats
// (jt stride = 72 floats = 8 banks -> conflict-free broadcasts).
// ---------------------------------------------------------------------------
__global__ void __launch_bounds__(512, 2) k2_pairs(
    const float* __restrict__ h_el_el,
    const float* __restrict__ Wsame, const float* __restrict__ bsame,
    const float* __restrict__ Wdiff, const float* __restrict__ bdiff,
    float* __restrict__ feats, float* __restrict__ mult)
{
    extern __shared__ __align__(16) float smf[];
    float* sW    = smf + K2_SW;      // [2][2048]
    float* sHM   = smf + K2_SHM;     // [32][64]
    float* sRed  = smf + K2_SRED;    // [2][4][4][64]
    float* sPair = smf + K2_SPAIR;   // [2][4][32][36]

    int b   = blockIdx.x;
    int tid = threadIdx.x;

    for (int t = tid; t < D2*EMB; t += 512) {
        sW[t]        = Wsame[t];
        sW[2048 + t] = Wdiff[t];
    }
    const float* hm = g_hmapped + (size_t)b*NEL*EMB;
    for (int t = tid; t < NEL*EMB; t += 512) sHM[t] = hm[t];

    const float* pb = h_el_el + (size_t)b*NEL*NEL*D2;
    // prefetch tile 0: rows i=0..3 (16KB) into padded layout
    #pragma unroll
    for (int it = 0; it < 2; it++) {
        int q   = tid + it*512;            // 0..1023 float4 units
        int row = q >> 3, part = q & 7;    // row = h*32 + j
        cp16(&sPair[row*K2_ROWPAD + part*4], pb + (size_t)q*4);
    }
    CP_COMMIT();

    int h  = tid >> 7;          // i within quad (0..3)
    int ht = tid & 127;
    int eg = ht & 7;   int e0 = eg*8;
    int jt = ht >> 3;  int j0 = jt*2;     // jt 0..15
    int lane = tid & 31;
    int w2   = ht >> 5;         // 0..3: warp within the h-half
    int selbase = (jt < 8) ? 0 : 1;       // warp-uniform (warp = 4 adjacent jt)

    float4 bS0 = __ldg((const float4*)(bsame + e0));
    float4 bS1 = __ldg((const float4*)(bsame + e0 + 4));
    float4 bD0 = __ldg((const float4*)(bdiff + e0));
    float4 bD1 = __ldg((const float4*)(bdiff + e0 + 4));

    CP_WAIT0();
    __syncthreads();

    for (int s = 0; s < 8; s++) {
        int cur = s & 1;
        if (s < 7) {
            const float* src = pb + (size_t)(s + 1)*4*NEL*D2;
            float* dst = &sPair[(cur ^ 1)*K2_TILE];
            #pragma unroll
            for (int it = 0; it < 2; it++) {
                int q   = tid + it*512;
                int row = q >> 3, part = q & 7;
                cp16(&dst[row*K2_ROWPAD + part*4], src + (size_t)q*4);
            }
            CP_COMMIT();
        }
        int i   = 4*s + h;
        int sel = selbase ^ ((s < 4) ? 0 : 1);   // i<16 <=> s<4
        const float* Wp   = sW + sel*2048;
        const float* prow = &sPair[cur*K2_TILE + h*NEL*K2_ROWPAD + j0*K2_ROWPAD];

        float4 a00 = sel ? bD0 : bS0;
        float4 a01 = sel ? bD1 : bS1;
        float4 a10 = a00, a11 = a01;
        #pragma unroll 8
        for (int k = 0; k < D2; k++) {
            float4 w0 = *(const float4*)&Wp[k*EMB + e0];
            float4 w1 = *(const float4*)&Wp[k*EMB + e0 + 4];
            float p0 = prow[k];
            float p1 = prow[K2_ROWPAD + k];
            a00.x = fmaf(p0, w0.x, a00.x); a00.y = fmaf(p0, w0.y, a00.y);
            a00.z = fmaf(p0, w0.z, a00.z); a00.w = fmaf(p0, w0.w, a00.w);
            a01.x = fmaf(p0, w1.x, a01.x); a01.y = fmaf(p0, w1.y, a01.y);
            a01.z = fmaf(p0, w1.z, a01.z); a01.w = fmaf(p0, w1.w, a01.w);
            a10.x = fmaf(p1, w0.x, a10.x); a10.y = fmaf(p1, w0.y, a10.y);
            a10.z = fmaf(p1, w0.z, a10.z); a10.w = fmaf(p1, w0.w, a10.w);
            a11.x = fmaf(p1, w1.x, a11.x); a11.y = fmaf(p1, w1.y, a11.y);
            a11.z = fmaf(p1, w1.z, a11.z); a11.w = fmaf(p1, w1.w, a11.w);
        }

        // epilogue: tanh * hm, store mult, accumulate el_el partial
        float4 hA0 = *(const float4*)&sHM[j0*EMB + e0];
        float4 hA1 = *(const float4*)&sHM[j0*EMB + e0 + 4];
        float4 hB0 = *(const float4*)&sHM[(j0 + 1)*EMB + e0];
        float4 hB1 = *(const float4*)&sHM[(j0 + 1)*EMB + e0 + 4];
        float4 o00, o01, o10, o11;
        o00.x = fast_tanh(a00.x)*hA0.x; o00.y = fast_tanh(a00.y)*hA0.y;
        o00.z = fast_tanh(a00.z)*hA0.z; o00.w = fast_tanh(a00.w)*hA0.w;
        o01.x = fast_tanh(a01.x)*hA1.x; o01.y = fast_tanh(a01.y)*hA1.y;
        o01.z = fast_tanh(a01.z)*hA1.z; o01.w = fast_tanh(a01.w)*hA1.w;
        o10.x = fast_tanh(a10.x)*hB0.x; o10.y = fast_tanh(a10.y)*hB0.y;
        o10.z = fast_tanh(a10.z)*hB0.z; o10.w = fast_tanh(a10.w)*hB0.w;
        o11.x = fast_tanh(a11.x)*hB1.x; o11.y = fast_tanh(a11.y)*hB1.y;
        o11.z = fast_tanh(a11.z)*hB1.z; o11.w = fast_tanh(a11.w)*hB1.w;

        float* mrow = mult + (((size_t)b*NEL + i)*NEL + j0)*EMB + e0;
        *(float4*)mrow            = o00;
        *(float4*)(mrow + 4)      = o01;
        *(float4*)(mrow + EMB)    = o10;
        *(float4*)(mrow + EMB + 4)= o11;

        // el_el partial: sum 2 j, then reduce the warp's 4 jt (stride-8 lanes)
        float4 s0 = make_float4(o00.x + o10.x, o00.y + o10.y,
                                o00.z + o10.z, o00.w + o10.w);
        float4 s1 = make_float4(o01.x + o11.x, o01.y + o11.y,
                                o01.z + o11.z, o01.w + o11.w);
        s0.x += __shfl_down_sync(0xffffffffu, s0.x, 16);
        s0.y += __shfl_down_sync(0xffffffffu, s0.y, 16);
        s0.z += __shfl_down_sync(0xffffffffu, s0.z, 16);
        s0.w += __shfl_down_sync(0xffffffffu, s0.w, 16);
        s1.x += __shfl_down_sync(0xffffffffu, s1.x, 16);
        s1.y += __shfl_down_sync(0xffffffffu, s1.y, 16);
        s1.z += __shfl_down_sync(0xffffffffu, s1.z, 16);
        s1.w += __shfl_down_sync(0xffffffffu, s1.w, 16);
        s0.x += __shfl_down_sync(0xffffffffu, s0.x, 8);
        s0.y += __shfl_down_sync(0xffffffffu, s0.y, 8);
        s0.z += __shfl_down_sync(0xffffffffu, s0.z, 8);
        s0.w += __shfl_down_sync(0xffffffffu, s0.w, 8);
        s1.x += __shfl_down_sync(0xffffffffu, s1.x, 8);
        s1.y += __shfl_down_sync(0xffffffffu, s1.y, 8);
        s1.z += __shfl_down_sync(0xffffffffu, s1.z, 8);
        s1.w += __shfl_down_sync(0xffffffffu, s1.w, 8);
        if (lane < 8) {
            float* rd = &sRed[(((cur*4 + h)*4) + w2)*EMB + e0];
            *(float4*)rd       = s0;
            *(float4*)(rd + 4) = s1;
        }

        // f_pairs (pre-barrier; raw tile reads)
        if (tid >= 256) {
            int t    = tid - 256;
            int hh   = t >> 6;
            int t3   = t & 63;
            int half = t3 >> 5;
            int cc   = t3 & 31;
            const float* tp = &sPair[cur*K2_TILE + hh*NEL*K2_ROWPAD];
            float sum = 0.f;
            #pragma unroll
            for (int jj = 0; jj < 16; jj++)
                sum += tp[(half*16 + jj)*K2_ROWPAD + cc];
            feats[(((size_t)b*NEL + 4*s + hh)*FEAT) + 768 + t3] = sum * (1.0f/16.0f);
        }

        if (s < 7) CP_WAIT0();
        __syncthreads();

        // el_el (post-barrier, overlaps next step's compute in other warps)
        if (tid < 256) {
            int hh = tid >> 6;
            int e  = tid & 63;
            float acc = sRed[((cur*4 + hh)*4 + 0)*EMB + e]
                      + sRed[((cur*4 + hh)*4 + 1)*EMB + e]
                      + sRed[((cur*4 + hh)*4 + 2)*EMB + e]
                      + sRed[((cur*4 + hh)*4 + 3)*EMB + e];
            feats[(((size_t)b*NEL + 4*s + hh)*FEAT) + 832 + e] = acc * (1.0f/16.0f);
        }
    }
}

// ---------------------------------------------------------------------------
extern "C" void kernel_launch(void* const* d_in, const int* in_sizes, int n_in,
                              void* d_out, int out_size)
{
    const float* h_one    = (const float*)d_in[0];
    const float* h_ion    = (const float*)d_in[1];
    const float* h_el_el  = (const float*)d_in[2];
    const float* h_el_ion = (const float*)d_in[3];
    const float* W_hmap   = (const float*)d_in[4];
    const float* b_hmap   = (const float*)d_in[5];
    const float* W_wsame  = (const float*)d_in[6];
    const float* b_wsame  = (const float*)d_in[7];
    const float* W_wdiff  = (const float*)d_in[8];
    const float* b_wdiff  = (const float*)d_in[9];
    const float* W_ion    = (const float*)d_in[10];
    const float* b_ion    = (const float*)d_in[11];

    float* out   = (float*)d_out;
    float* feats = out;
    float* mult  = out + ((size_t)out_size - MULT_ELEMS);

    cudaFuncSetAttribute(k2_pairs, cudaFuncAttributeMaxDynamicSharedMemorySize,
                         K2_SMEM_BYTES);

    k13_fused<<<BATCH, 256>>>(h_one, W_hmap, b_hmap, h_ion, h_el_ion,
                              W_ion, b_ion, feats);
    k2_pairs<<<BATCH, 512, K2_SMEM_BYTES>>>(h_el_el, W_wsame, b_wsame,
                                            W_wdiff, b_wdiff, feats, mult);
}

// round 15
// speedup vs baseline: 1.7048x; 1.7048x over previous
#include <cuda_runtime.h>
#include <cstdint>

#define BATCH 1024
#define NEL 32
#define NUP 16
#define NION 8
#define D1 256
#define D2 32
#define DION 64
#define DELION 32
#define EMB 64
#define FEAT 928
#define MULT_ELEMS (BATCH*NEL*NEL*EMB)   // 67108864

// K2 dynamic smem layout (floats)
#define K2_SW     0          // [2][2048] = 4096
#define K2_SHM    4096       // 2048
#define K2_SRED   6144       // [2][4][4][64] = 2048
#define K2_SPAIR  8192       // 2 x (4 rows x 32 j x 36 k) = 2*4608
#define K2_ROWPAD 36
#define K2_TILE   4608       // 4*32*36
#define K2_SMEM_BYTES ((8192 + 2*4608) * 4)         // 69632

__device__ float g_hmapped[BATCH*NEL*EMB];       // 8 MB

// rel err ~1e-6 tanh: 2 MUFU + few ALU
__device__ __forceinline__ float fast_tanh(float x) {
    float ax = fabsf(x);
    float e  = __expf(-2.0f * ax);
    float r  = __fdividef(1.0f - e, 1.0f + e);
    return copysignf(r, x);
}

__device__ __forceinline__ void cp16(void* dst_smem, const void* src) {
    unsigned d = (unsigned)__cvta_generic_to_shared(dst_smem);
    asm volatile("cp.async.cg.shared.global [%0], [%1], 16;\n" :: "r"(d), "l"(src));
}
#define CP_COMMIT() asm volatile("cp.async.commit_group;\n")
#define CP_WAIT0()  asm volatile("cp.async.wait_group 0;\n" ::: "memory")

// ---------------------------------------------------------------------------
// K13: fused h_mapped GEMM + spin averages + ion mapping + feats assembly.
// (static-smem version, measured 73us)
// ---------------------------------------------------------------------------
__global__ void __launch_bounds__(256, 3) k13_fused(
    const float* __restrict__ h_one,
    const float* __restrict__ W,      // (256,64)
    const float* __restrict__ bias,   // (64,)
    const float* __restrict__ h_ion,
    const float* __restrict__ h_el_ion,
    const float* __restrict__ W_ion, const float* __restrict__ b_ion,
    float* __restrict__ feats)
{
    __shared__ __align__(16) float sH[NEL*D1];       // 32 KB
    __shared__ float sI[NION*DION];                  // 2 KB
    __shared__ float sIon[NION*DELION];              // 1 KB
    int b = blockIdx.x;
    const float4* hb4 = (const float4*)(h_one + (size_t)b*NEL*D1);
    #pragma unroll
    for (int t = 0; t < 8; t++)
        ((float4*)sH)[threadIdx.x + t*256] = hb4[threadIdx.x + t*256];
    for (int t = threadIdx.x; t < NION*DION; t += 256)
        sI[t] = h_ion[(size_t)b*NION*DION + t];
    __syncthreads();

    // ion mapping: one (a,c) per thread
    {
        int c = threadIdx.x & 31;
        int a = threadIdx.x >> 5;
        float acc = __ldg(b_ion + c);
        #pragma unroll 4
        for (int k = 0; k < DION; k++)
            acc = fmaf(sI[a*DION + k], __ldg(W_ion + k*DELION + c), acc);
        sIon[a*DELION + c] = fast_tanh(acc);
    }

    // h_mapped GEMM: 4 rows x 2 cols per thread
    int et = threadIdx.x & 31;   int e0 = et*2;
    int it = threadIdx.x >> 5;

    float2 bv = __ldg((const float2*)(bias + e0));
    float2 acc[4];
    #pragma unroll
    for (int r = 0; r < 4; r++) acc[r] = bv;

    #pragma unroll 4
    for (int k = 0; k < D1; k += 4) {
        float h[4][4];
        #pragma unroll
        for (int r = 0; r < 4; r++) {
            float4 v = *(const float4*)&sH[(it*4 + r)*D1 + k];
            h[r][0] = v.x; h[r][1] = v.y; h[r][2] = v.z; h[r][3] = v.w;
        }
        #pragma unroll
        for (int t = 0; t < 4; t++) {
            float2 w = __ldg((const float2*)(W + (k + t)*EMB + e0));
            #pragma unroll
            for (int r = 0; r < 4; r++) {
                acc[r].x = fmaf(h[r][t], w.x, acc[r].x);
                acc[r].y = fmaf(h[r][t], w.y, acc[r].y);
            }
        }
    }
    float* o = g_hmapped + (size_t)b*NEL*EMB;
    #pragma unroll
    for (int r = 0; r < 4; r++) {
        float2 ov = make_float2(fast_tanh(acc[r].x), fast_tanh(acc[r].y));
        *(float2*)&o[(it*4 + r)*EMB + e0] = ov;
    }

    // spin averages of h_one (per-thread feature d)
    int d = threadIdx.x;
    float su = 0.f, sd = 0.f;
    #pragma unroll
    for (int i = 0; i < NUP; i++)  su += sH[i*D1 + d];
    #pragma unroll
    for (int i = NUP; i < NEL; i++) sd += sH[i*D1 + d];
    float au = su * (1.0f/NUP);
    float ad = sd * (1.0f/(NEL - NUP));

    __syncthreads();   // sIon ready

    // feats: h_one copy + tiles
    for (int i = 0; i < NEL; i++) {
        float* fb = feats + ((size_t)b*NEL + i)*FEAT;
        fb[d]        = sH[i*D1 + d];
        fb[D1 + d]   = au;
        fb[2*D1 + d] = ad;
    }

    // el_ion
    int c  = threadIdx.x & 31;
    int ig = threadIdx.x >> 5;
    #pragma unroll
    for (int r = 0; r < 4; r++) {
        int i = ig + r*8;
        const float* he = h_el_ion + (((size_t)b*NEL + i)*NION)*DELION;
        float acc2 = 0.f;
        #pragma unroll
        for (int a = 0; a < NION; a++)
            acc2 += he[a*DELION + c] * sIon[a*DELION + c];
        feats[((size_t)b*NEL + i)*FEAT + 896 + c] = acc2 * (1.0f/NION);
    }
}

// ---------------------------------------------------------------------------
// K2: pair GEMM + tanh + multiply -> el_el_mult, el_el, f_pairs.
// 512 threads, 4 i-rows/step (8 steps), thread tile 4j x 4e.
// k blocked by 4: pair values loaded as LDS.128 along k (1 wf each, 2 distinct
// jt per warp), W as LDS.128 (2 wf) -> 3 wf/k vs 8 FMA-cyc/k  => FMA-bound.
// ---------------------------------------------------------------------------
__global__ void __launch_bounds__(512, 2) k2_pairs(
    const float* __restrict__ h_el_el,
    const float* __restrict__ Wsame, const float* __restrict__ bsame,
    const float* __restrict__ Wdiff, const float* __restrict__ bdiff,
    float* __restrict__ feats, float* __restrict__ mult)
{
    extern __shared__ __align__(16) float smf[];
    float* sW    = smf + K2_SW;      // [2][2048]
    float* sHM   = smf + K2_SHM;     // [32][64]
    float* sRed  = smf + K2_SRED;    // [2][4][4][64]
    float* sPair = smf + K2_SPAIR;   // [2][4][32][36]

    int b   = blockIdx.x;
    int tid = threadIdx.x;

    for (int t = tid; t < D2*EMB; t += 512) {
        sW[t]        = Wsame[t];
        sW[2048 + t] = Wdiff[t];
    }
    const float* hm = g_hmapped + (size_t)b*NEL*EMB;
    for (int t = tid; t < NEL*EMB; t += 512) sHM[t] = hm[t];

    const float* pb = h_el_el + (size_t)b*NEL*NEL*D2;
    // prefetch tile 0: rows i=0..3 (16KB) into padded layout
    #pragma unroll
    for (int it = 0; it < 2; it++) {
        int q   = tid + it*512;            // 0..1023 float4 units
        int row = q >> 3, part = q & 7;    // row = h*32 + j
        cp16(&sPair[row*K2_ROWPAD + part*4], pb + (size_t)q*4);
    }
    CP_COMMIT();

    int h  = tid >> 7;          // i within quad
    int ht = tid & 127;
    int eg = ht & 15;  int e0 = eg*4;
    int jt = ht >> 4;  int j0 = jt*4;     // jt 0..7
    int lane = tid & 31;
    int w2   = ht >> 5;         // 0..3: warp within the h-half
    int selbase = (jt < 4) ? 0 : 1;

    float4 bvS = __ldg((const float4*)(bsame + e0));
    float4 bvD = __ldg((const float4*)(bdiff + e0));

    CP_WAIT0();
    __syncthreads();

    for (int s = 0; s < 8; s++) {
        int cur = s & 1;
        if (s < 7) {
            const float* src = pb + (size_t)(s + 1)*4*NEL*D2;
            float* dst = &sPair[(cur ^ 1)*K2_TILE];
            #pragma unroll
            for (int it = 0; it < 2; it++) {
                int q   = tid + it*512;
                int row = q >> 3, part = q & 7;
                cp16(&dst[row*K2_ROWPAD + part*4], src + (size_t)q*4);
            }
            CP_COMMIT();
        }
        int i   = 4*s + h;
        int sel = selbase ^ ((s < 4) ? 0 : 1);   // i<16 <=> s<4
        const float* Wp   = sW + sel*2048;
        const float* prow = &sPair[cur*K2_TILE + h*NEL*K2_ROWPAD + j0*K2_ROWPAD];

        float4 bv = sel ? bvD : bvS;
        float4 a0 = bv, a1 = bv, a2 = bv, a3 = bv;
        #pragma unroll
        for (int k4 = 0; k4 < D2/4; k4++) {
            // pair values: one LDS.128 per j-row per 4 k (k-contiguous layout)
            float4 P0 = *(const float4*)&prow[k4*4];
            float4 P1 = *(const float4*)&prow[K2_ROWPAD + k4*4];
            float4 P2 = *(const float4*)&prow[2*K2_ROWPAD + k4*4];
            float4 P3 = *(const float4*)&prow[3*K2_ROWPAD + k4*4];
            const float* p0 = (const float*)&P0;
            const float* p1 = (const float*)&P1;
            const float* p2 = (const float*)&P2;
            const float* p3 = (const float*)&P3;
            #pragma unroll
            for (int u = 0; u < 4; u++) {
                float4 wv = *(const float4*)&Wp[(k4*4 + u)*EMB + e0];
                a0.x = fmaf(p0[u], wv.x, a0.x); a0.y = fmaf(p0[u], wv.y, a0.y);
                a0.z = fmaf(p0[u], wv.z, a0.z); a0.w = fmaf(p0[u], wv.w, a0.w);
                a1.x = fmaf(p1[u], wv.x, a1.x); a1.y = fmaf(p1[u], wv.y, a1.y);
                a1.z = fmaf(p1[u], wv.z, a1.z); a1.w = fmaf(p1[u], wv.w, a1.w);
                a2.x = fmaf(p2[u], wv.x, a2.x); a2.y = fmaf(p2[u], wv.y, a2.y);
                a2.z = fmaf(p2[u], wv.z, a2.z); a2.w = fmaf(p2[u], wv.w, a2.w);
                a3.x = fmaf(p3[u], wv.x, a3.x); a3.y = fmaf(p3[u], wv.y, a3.y);
                a3.z = fmaf(p3[u], wv.z, a3.z); a3.w = fmaf(p3[u], wv.w, a3.w);
            }
        }

        // epilogue: tanh * hm, store mult, accumulate el_el partial
        float4 s4 = make_float4(0.f, 0.f, 0.f, 0.f);
        float* mrow = mult + (((size_t)b*NEL + i)*NEL + j0)*EMB + e0;
        float4 av[4] = {a0, a1, a2, a3};
        #pragma unroll
        for (int jj = 0; jj < 4; jj++) {
            float4 hm4 = *(const float4*)&sHM[(j0 + jj)*EMB + e0];
            float4 o;
            o.x = fast_tanh(av[jj].x)*hm4.x;
            o.y = fast_tanh(av[jj].y)*hm4.y;
            o.z = fast_tanh(av[jj].z)*hm4.z;
            o.w = fast_tanh(av[jj].w)*hm4.w;
            *(float4*)(mrow + jj*EMB) = o;
            s4.x += o.x; s4.y += o.y; s4.z += o.z; s4.w += o.w;
        }
        // combine warp's jt pair (lanes 16-31 -> 0-15)
        s4.x += __shfl_down_sync(0xffffffffu, s4.x, 16);
        s4.y += __shfl_down_sync(0xffffffffu, s4.y, 16);
        s4.z += __shfl_down_sync(0xffffffffu, s4.z, 16);
        s4.w += __shfl_down_sync(0xffffffffu, s4.w, 16);
        if (lane < 16)
            *(float4*)&sRed[(((cur*4 + h)*4) + w2)*EMB + lane*4] = s4;

        // f_pairs (pre-barrier; raw tile reads)
        if (tid >= 256) {
            int t    = tid - 256;
            int hh   = t >> 6;
            int t3   = t & 63;
            int half = t3 >> 5;
            int cc   = t3 & 31;
            const float* tp = &sPair[cur*K2_TILE + hh*NEL*K2_ROWPAD];
            float sum = 0.f;
            #pragma unroll
            for (int jj = 0; jj < 16; jj++)
                sum += tp[(half*16 + jj)*K2_ROWPAD + cc];
            feats[(((size_t)b*NEL + 4*s + hh)*FEAT) + 768 + t3] = sum * (1.0f/16.0f);
        }

        if (s < 7) CP_WAIT0();
        __syncthreads();

        // el_el (post-barrier, overlaps next step's compute in other warps)
        if (tid < 256) {
            int hh = tid >> 6;
            int e  = tid & 63;
            float acc = sRed[((cur*4 + hh)*4 + 0)*EMB + e]
                      + sRed[((cur*4 + hh)*4 + 1)*EMB + e]
                      + sRed[((cur*4 + hh)*4 + 2)*EMB + e]
                      + sRed[((cur*4 + hh)*4 + 3)*EMB + e];
            feats[(((size_t)b*NEL + 4*s + hh)*FEAT) + 832 + e] = acc * (1.0f/16.0f);
        }
    }
}

// ---------------------------------------------------------------------------
extern "C" void kernel_launch(void* const* d_in, const int* in_sizes, int n_in,
                              void* d_out, int out_size)
{
    const float* h_one    = (const float*)d_in[0];
    const float* h_ion    = (const float*)d_in[1];
    const float* h_el_el  = (const float*)d_in[2];
    const float* h_el_ion = (const float*)d_in[3];
    const float* W_hmap   = (const float*)d_in[4];
    const float* b_hmap   = (const float*)d_in[5];
    const float* W_wsame  = (const float*)d_in[6];
    const float* b_wsame  = (const float*)d_in[7];
    const float* W_wdiff  = (const float*)d_in[8];
    const float* b_wdiff  = (const float*)d_in[9];
    const float* W_ion    = (const float*)d_in[10];
    const float* b_ion    = (const float*)d_in[11];

    float* out   = (float*)d_out;
    float* feats = out;
    float* mult  = out + ((size_t)out_size - MULT_ELEMS);

    cudaFuncSetAttribute(k2_pairs, cudaFuncAttributeMaxDynamicSharedMemorySize,
                         K2_SMEM_BYTES);

    k13_fused<<<BATCH, 256>>>(h_one, W_hmap, b_hmap, h_ion, h_el_ion,
                              W_ion, b_ion, feats);
    k2_pairs<<<BATCH, 512, K2_SMEM_BYTES>>>(h_el_el, W_wsame, b_wsame,
                                            W_wdiff, b_wdiff, feats, mult);
}

// round 17
// speedup vs baseline: 1.7712x; 1.0390x over previous
#include <cuda_runtime.h>
#include <cuda_bf16.h>
#include <cstdint>

#define BATCH 1024
#define NEL 32
#define NUP 16
#define NION 8
#define D1 256
#define D2 32
#define DION 64
#define DELION 32
#define EMB 64
#define FEAT 928
#define MULT_ELEMS (BATCH*NEL*NEL*EMB)   // 67108864

// K2 dynamic smem layout (bytes)
#define ST_STAGE 0          // fp32 pair tiles [2][4][32][36] = 36864
#define ST_AHI   36864      // bf16x2 words [128][20] = 10240
#define ST_ALO   47104      // 10240
#define ST_B     57344      // W bf16x2 words [2 sel][2 term][64][20] = 20480
#define ST_HM    77824      // [32][66] f32 = 8448
#define ST_RED   86272      // [2][4][2][64] f32 = 4096
#define ST_BIAS  90368      // [2][64] f32 = 512
#define K2_SMEM  90880

__device__ float g_hmapped[BATCH*NEL*EMB];       // 8 MB

// rel err ~1e-6 tanh: 2 MUFU + few ALU
__device__ __forceinline__ float fast_tanh(float x) {
    float ax = fabsf(x);
    float e  = __expf(-2.0f * ax);
    float r  = __fdividef(1.0f - e, 1.0f + e);
    return copysignf(r, x);
}

__device__ __forceinline__ void cp16(void* dst_smem, const void* src) {
    unsigned d = (unsigned)__cvta_generic_to_shared(dst_smem);
    asm volatile("cp.async.cg.shared.global [%0], [%1], 16;\n" :: "r"(d), "l"(src));
}
#define CP_COMMIT() asm volatile("cp.async.commit_group;\n")
#define CP_WAIT0()  asm volatile("cp.async.wait_group 0;\n" ::: "memory")

// mma.sync m16n8k16 bf16 (row.col), D/C fp32, accumulate in place
__device__ __forceinline__ void mma_bf16(float* c, uint32_t a0, uint32_t a1,
                                         uint32_t a2, uint32_t a3,
                                         uint32_t b0, uint32_t b1) {
    asm volatile(
        "mma.sync.aligned.m16n8k16.row.col.f32.bf16.bf16.f32 "
        "{%0,%1,%2,%3}, {%4,%5,%6,%7}, {%8,%9}, {%0,%1,%2,%3};"
        : "+f"(c[0]), "+f"(c[1]), "+f"(c[2]), "+f"(c[3])
        : "r"(a0), "r"(a1), "r"(a2), "r"(a3), "r"(b0), "r"(b1));
}

__device__ __forceinline__ uint32_t pack_bf16x2(float lo, float hi) {
    __nv_bfloat162 p = __halves2bfloat162(__float2bfloat16(lo), __float2bfloat16(hi));
    return *(uint32_t*)&p;
}

// ---------------------------------------------------------------------------
// K13: fused h_mapped GEMM + spin averages + ion mapping + feats assembly.
// (measured 73us, unchanged)
// ---------------------------------------------------------------------------
__global__ void __launch_bounds__(256, 3) k13_fused(
    const float* __restrict__ h_one,
    const float* __restrict__ W,      // (256,64)
    const float* __restrict__ bias,   // (64,)
    const float* __restrict__ h_ion,
    const float* __restrict__ h_el_ion,
    const float* __restrict__ W_ion, const float* __restrict__ b_ion,
    float* __restrict__ feats)
{
    __shared__ __align__(16) float sH[NEL*D1];       // 32 KB
    __shared__ float sI[NION*DION];                  // 2 KB
    __shared__ float sIon[NION*DELION];              // 1 KB
    int b = blockIdx.x;
    const float4* hb4 = (const float4*)(h_one + (size_t)b*NEL*D1);
    #pragma unroll
    for (int t = 0; t < 8; t++)
        ((float4*)sH)[threadIdx.x + t*256] = hb4[threadIdx.x + t*256];
    for (int t = threadIdx.x; t < NION*DION; t += 256)
        sI[t] = h_ion[(size_t)b*NION*DION + t];
    __syncthreads();

    {
        int c = threadIdx.x & 31;
        int a = threadIdx.x >> 5;
        float acc = __ldg(b_ion + c);
        #pragma unroll 4
        for (int k = 0; k < DION; k++)
            acc = fmaf(sI[a*DION + k], __ldg(W_ion + k*DELION + c), acc);
        sIon[a*DELION + c] = fast_tanh(acc);
    }

    int et = threadIdx.x & 31;   int e0 = et*2;
    int it = threadIdx.x >> 5;

    float2 bv = __ldg((const float2*)(bias + e0));
    float2 acc[4];
    #pragma unroll
    for (int r = 0; r < 4; r++) acc[r] = bv;

    #pragma unroll 4
    for (int k = 0; k < D1; k += 4) {
        float h[4][4];
        #pragma unroll
        for (int r = 0; r < 4; r++) {
            float4 v = *(const float4*)&sH[(it*4 + r)*D1 + k];
            h[r][0] = v.x; h[r][1] = v.y; h[r][2] = v.z; h[r][3] = v.w;
        }
        #pragma unroll
        for (int t = 0; t < 4; t++) {
            float2 w = __ldg((const float2*)(W + (k + t)*EMB + e0));
            #pragma unroll
            for (int r = 0; r < 4; r++) {
                acc[r].x = fmaf(h[r][t], w.x, acc[r].x);
                acc[r].y = fmaf(h[r][t], w.y, acc[r].y);
            }
        }
    }
    float* o = g_hmapped + (size_t)b*NEL*EMB;
    #pragma unroll
    for (int r = 0; r < 4; r++) {
        float2 ov = make_float2(fast_tanh(acc[r].x), fast_tanh(acc[r].y));
        *(float2*)&o[(it*4 + r)*EMB + e0] = ov;
    }

    int d = threadIdx.x;
    float su = 0.f, sd = 0.f;
    #pragma unroll
    for (int i = 0; i < NUP; i++)  su += sH[i*D1 + d];
    #pragma unroll
    for (int i = NUP; i < NEL; i++) sd += sH[i*D1 + d];
    float au = su * (1.0f/NUP);
    float ad = sd * (1.0f/(NEL - NUP));

    __syncthreads();

    for (int i = 0; i < NEL; i++) {
        float* fb = feats + ((size_t)b*NEL + i)*FEAT;
        fb[d]        = sH[i*D1 + d];
        fb[D1 + d]   = au;
        fb[2*D1 + d] = ad;
    }

    int c  = threadIdx.x & 31;
    int ig = threadIdx.x >> 5;
    #pragma unroll
    for (int r = 0; r < 4; r++) {
        int i = ig + r*8;
        const float* he = h_el_ion + (((size_t)b*NEL + i)*NION)*DELION;
        float acc2 = 0.f;
        #pragma unroll
        for (int a = 0; a < NION; a++)
            acc2 += he[a*DELION + c] * sIon[a*DELION + c];
        feats[((size_t)b*NEL + i)*FEAT + 896 + c] = acc2 * (1.0f/NION);
    }
}

// ---------------------------------------------------------------------------
// K2 (mma.sync bf16 3-term split): per step 4 i-rows -> GEMM M=128,N=64,K=32.
// 16 warps: warp = (16-row M-slice ms=0..7, N-half 0..1).  sel warp-uniform.
// fp32 tiles cp.async double-buffered; conversion packs bf16 hi/lo words
// stride-20 (conflict-free frag loads).  Epilogue straight from D regs.
// ---------------------------------------------------------------------------
__global__ void __launch_bounds__(512, 2) k2_mma(
    const float* __restrict__ h_el_el,
    const float* __restrict__ Wsame, const float* __restrict__ bsame,
    const float* __restrict__ Wdiff, const float* __restrict__ bdiff,
    float* __restrict__ feats, float* __restrict__ mult)
{
    extern __shared__ __align__(16) char smc[];
    float*    stage = (float*)(smc + ST_STAGE);    // [2][128][36] fp32
    uint32_t* sAhi  = (uint32_t*)(smc + ST_AHI);   // [128][20] bf16x2
    uint32_t* sAlo  = (uint32_t*)(smc + ST_ALO);
    uint32_t* sBw   = (uint32_t*)(smc + ST_B);     // [sel][term][64][20]
    float*    sHM   = (float*)(smc + ST_HM);       // [32][66]
    float*    sRed  = (float*)(smc + ST_RED);      // [2][4][2][64]
    float*    sBias = (float*)(smc + ST_BIAS);     // [2][64]

    int b    = blockIdx.x;
    int tid  = threadIdx.x;
    int lane = tid & 31, wid = tid >> 5;
    int gid  = lane >> 2, four = lane & 3;
    int ms    = wid >> 1;        // M-slice 0..7 (= h*2 + jhalf)
    int nhalf = wid & 1;
    int hh    = ms >> 1;
    int jhalf = ms & 1;

    // ---- preamble: W -> bf16 hi/lo words (k-pairs), bias, hm ----
    #pragma unroll
    for (int rep = 0; rep < 2; rep++) {
        int idx = tid + rep*512;           // 0..1023 = 64 e x 16 words
        int e = idx >> 4, w = idx & 15;
        float s0 = __ldg(Wsame + (2*w)*EMB + e);
        float s1 = __ldg(Wsame + (2*w+1)*EMB + e);
        __nv_bfloat16 h0 = __float2bfloat16(s0), h1 = __float2bfloat16(s1);
        sBw[e*20 + w]        = pack_bf16x2(__bfloat162float(h0), __bfloat162float(h1));
        sBw[1280 + e*20 + w] = pack_bf16x2(s0 - __bfloat162float(h0),
                                           s1 - __bfloat162float(h1));
        float d0 = __ldg(Wdiff + (2*w)*EMB + e);
        float d1 = __ldg(Wdiff + (2*w+1)*EMB + e);
        __nv_bfloat16 g0 = __float2bfloat16(d0), g1 = __float2bfloat16(d1);
        sBw[2560 + e*20 + w] = pack_bf16x2(__bfloat162float(g0), __bfloat162float(g1));
        sBw[3840 + e*20 + w] = pack_bf16x2(d0 - __bfloat162float(g0),
                                           d1 - __bfloat162float(g1));
    }
    if (tid < 64) {
        sBias[tid]      = __ldg(bsame + tid);
        sBias[64 + tid] = __ldg(bdiff + tid);
    }
    const float* hm = g_hmapped + (size_t)b*NEL*EMB;
    #pragma unroll
    for (int rep = 0; rep < 4; rep++) {
        int idx = tid + rep*512;
        sHM[(idx >> 6)*66 + (idx & 63)] = hm[idx];
    }

    const float* pb = h_el_el + (size_t)b*NEL*NEL*D2;
    #pragma unroll
    for (int it = 0; it < 2; it++) {
        int q = tid + it*512, row = q >> 3, part = q & 7;
        cp16(&stage[row*36 + part*4], pb + (size_t)q*4);
    }
    CP_COMMIT();
    CP_WAIT0();
    __syncthreads();

    for (int s = 0; s < 8; s++) {
        int cur = s & 1;

        // ---- convert fp32 -> bf16 hi/lo (each thread: 1 row-chunk of 8 k) ----
        {
            int r = tid >> 2, ch = tid & 3;
            const float* sp = &stage[cur*4608 + r*36 + ch*8];
            float4 v0 = *(const float4*)sp;
            float4 v1 = *(const float4*)(sp + 4);
            float x[8] = {v0.x, v0.y, v0.z, v0.w, v1.x, v1.y, v1.z, v1.w};
            uint32_t* dh = &sAhi[r*20 + ch*4];
            uint32_t* dl = &sAlo[r*20 + ch*4];
            #pragma unroll
            for (int m = 0; m < 4; m++) {
                __nv_bfloat16 ha = __float2bfloat16(x[2*m]);
                __nv_bfloat16 hb = __float2bfloat16(x[2*m+1]);
                dh[m] = pack_bf16x2(__bfloat162float(ha), __bfloat162float(hb));
                dl[m] = pack_bf16x2(x[2*m]   - __bfloat162float(ha),
                                    x[2*m+1] - __bfloat162float(hb));
            }
        }
        if (s < 7) {
            const float* src = pb + (size_t)(s + 1)*4*NEL*D2;
            float* dst = &stage[(cur ^ 1)*4608];
            #pragma unroll
            for (int it = 0; it < 2; it++) {
                int q = tid + it*512, row = q >> 3, part = q & 7;
                cp16(&dst[row*36 + part*4], src + (size_t)q*4);
            }
            CP_COMMIT();
        }
        __syncthreads();   // bf16 tile ready

        int sel = jhalf ^ ((s >= 4) ? 1 : 0);
        const uint32_t* Bh = sBw + sel*2560;
        const uint32_t* Bl = Bh + 1280;

        float c[4][4];
        #pragma unroll
        for (int nt = 0; nt < 4; nt++) {
            c[nt][0] = 0.f; c[nt][1] = 0.f; c[nt][2] = 0.f; c[nt][3] = 0.f;
        }
        #pragma unroll
        for (int ks = 0; ks < 2; ks++) {
            int aw = (ms*16 + gid)*20 + 8*ks + four;
            uint32_t ah0 = sAhi[aw],       ah1 = sAhi[aw + 160];
            uint32_t ah2 = sAhi[aw + 4],   ah3 = sAhi[aw + 164];
            uint32_t al0 = sAlo[aw],       al1 = sAlo[aw + 160];
            uint32_t al2 = sAlo[aw + 4],   al3 = sAlo[aw + 164];
            #pragma unroll
            for (int nt = 0; nt < 4; nt++) {
                int bw = (nhalf*32 + nt*8 + gid)*20 + 8*ks + four;
                uint32_t bh0 = Bh[bw], bh1 = Bh[bw + 4];
                uint32_t bl0 = Bl[bw], bl1 = Bl[bw + 4];
                mma_bf16(c[nt], ah0, ah1, ah2, ah3, bh0, bh1);
                mma_bf16(c[nt], al0, al1, al2, al3, bh0, bh1);
                mma_bf16(c[nt], ah0, ah1, ah2, ah3, bl0, bl1);
            }
        }

        // ---- epilogue from D regs: bias + tanh * hm -> mult, el_el partial ----
        int i  = 4*s + hh;
        int jA = jhalf*16 + gid, jB = jA + 8;
        float sE[8];
        #pragma unroll
        for (int nt = 0; nt < 4; nt++) {
            int e0 = nhalf*32 + nt*8 + 2*four;
            float2 bb = *(float2*)&sBias[sel*64 + e0];
            float2 hA = *(float2*)&sHM[jA*66 + e0];
            float2 hB = *(float2*)&sHM[jB*66 + e0];
            float x0 = fast_tanh(c[nt][0] + bb.x) * hA.x;
            float x1 = fast_tanh(c[nt][1] + bb.y) * hA.y;
            float x2 = fast_tanh(c[nt][2] + bb.x) * hB.x;
            float x3 = fast_tanh(c[nt][3] + bb.y) * hB.y;
            *(float2*)(mult + (((size_t)b*NEL + i)*NEL + jA)*EMB + e0) = make_float2(x0, x1);
            *(float2*)(mult + (((size_t)b*NEL + i)*NEL + jB)*EMB + e0) = make_float2(x2, x3);
            sE[2*nt]     = x0 + x2;
            sE[2*nt + 1] = x1 + x3;
        }
        #pragma unroll
        for (int d = 16; d >= 4; d >>= 1) {
            #pragma unroll
            for (int v = 0; v < 8; v++)
                sE[v] += __shfl_down_sync(0xffffffffu, sE[v], d);
        }
        if (lane < 4) {
            float* rd = &sRed[((cur*4 + hh)*2 + jhalf)*64 + nhalf*32];
            #pragma unroll
            for (int nt = 0; nt < 4; nt++)
                *(float2*)&rd[nt*8 + 2*four] = make_float2(sE[2*nt], sE[2*nt + 1]);
        }

        // f_pairs (exact, from raw fp32 stage)
        if (tid >= 256) {
            int t    = tid - 256;
            int h2   = t >> 6;
            int t3   = t & 63;
            int half = t3 >> 5;
            int cc   = t3 & 31;
            const float* tp = &stage[cur*4608 + h2*NEL*36];
            float sum = 0.f;
            #pragma unroll
            for (int jj = 0; jj < 16; jj++)
                sum += tp[(half*16 + jj)*36 + cc];
            feats[(((size_t)b*NEL + 4*s + h2)*FEAT) + 768 + t3] = sum * (1.0f/16.0f);
        }

        if (s < 7) CP_WAIT0();
        __syncthreads();   // sRed ready; next stage visible; bf16 tile consumed

        if (tid < 256) {
            int h2 = tid >> 6, e = tid & 63;
            float acc = sRed[((cur*4 + h2)*2 + 0)*64 + e]
                      + sRed[((cur*4 + h2)*2 + 1)*64 + e];
            feats[(((size_t)b*NEL + 4*s + h2)*FEAT) + 832 + e] = acc * (1.0f/16.0f);
        }
    }
}

// ---------------------------------------------------------------------------
extern "C" void kernel_launch(void* const* d_in, const int* in_sizes, int n_in,
                              void* d_out, int out_size)
{
    const float* h_one    = (const float*)d_in[0];
    const float* h_ion    = (const float*)d_in[1];
    const float* h_el_el  = (const float*)d_in[2];
    const float* h_el_ion = (const float*)d_in[3];
    const float* W_hmap   = (const float*)d_in[4];
    const float* b_hmap   = (const float*)d_in[5];
    const float* W_wsame  = (const float*)d_in[6];
    const float* b_wsame  = (const float*)d_in[7];
    const float* W_wdiff  = (const float*)d_in[8];
    const float* b_wdiff  = (const float*)d_in[9];
    const float* W_ion    = (const float*)d_in[10];
    const float* b_ion    = (const float*)d_in[11];

    float* out   = (float*)d_out;
    float* feats = out;
    float* mult  = out + ((size_t)out_size - MULT_ELEMS);

    cudaFuncSetAttribute(k2_mma, cudaFuncAttributeMaxDynamicSharedMemorySize,
                         K2_SMEM);

    k13_fused<<<BATCH, 256>>>(h_one, W_hmap, b_hmap, h_ion, h_el_ion,
                              W_ion, b_ion, feats);
    k2_mma<<<BATCH, 512, K2_SMEM>>>(h_el_el, W_wsame, b_wsame,
                                    W_wdiff, b_wdiff, feats, mult);
}